// round 15
// baseline (speedup 1.0000x reference)
#include <cuda_runtime.h>
#include <cuda_bf16.h>
#include <cstdint>
#include <cstddef>

// Problem constants
#define Bb 2
#define Ss 512
#define Hh 8
#define Dd 64
#define Ee 512
#define QT 32            // q rows per block
#define NRU 256          // relative index r
#define ROWB 144         // bf16 tile row stride in BYTES (16B rotation -> ldmatrix conflict-free)
#define PUP 258          // sPu pitch
#define NT 512           // threads per block (16 warps)

// Dynamic smem offsets (bytes)
#define OFF_QHI 0
#define OFF_QLO (QT * ROWB)                   //  4608
#define OFF_EHI (2 * QT * ROWB)               //  9216
#define OFF_ELO (2 * QT * ROWB + NRU * ROWB)  // 46080
#define DYN_BYTES (2 * QT * ROWB + 2 * NRU * ROWB)   // 82944; sPu (32*258*4=33024) overlays

// Pre-split E tables (bf16 hi/lo), written by esplit_kernel each launch. 512 KB, L2-resident.
__device__ __nv_bfloat16 g_ehi[NRU * Ee];
__device__ __nv_bfloat16 g_elo[NRU * Ee];

__device__ __forceinline__ uint32_t smem_u32(const void* p) {
    uint32_t a;
    asm("{ .reg .u64 t; cvta.to.shared.u64 t, %1; cvt.u32.u64 %0, t; }" : "=r"(a) : "l"(p));
    return a;
}
__device__ __forceinline__ uint32_t pack2(float a, float b) {
    __nv_bfloat162 t = __floats2bfloat162_rn(a, b);   // .x = a (low half)
    return *reinterpret_cast<uint32_t*>(&t);
}
__device__ __forceinline__ void ldsm_x4(uint32_t (&r)[4], uint32_t addr) {
    asm volatile("ldmatrix.sync.aligned.m8n8.x4.shared.b16 {%0,%1,%2,%3}, [%4];"
                 : "=r"(r[0]), "=r"(r[1]), "=r"(r[2]), "=r"(r[3]) : "r"(addr));
}
__device__ __forceinline__ void mma_bf16_r(float (&c)[4], const uint32_t (&a)[4],
                                           uint32_t b0, uint32_t b1) {
    asm volatile("mma.sync.aligned.m16n8k16.row.col.f32.bf16.bf16.f32 "
                 "{%0,%1,%2,%3}, {%4,%5,%6,%7}, {%8,%9}, {%0,%1,%2,%3};"
                 : "+f"(c[0]), "+f"(c[1]), "+f"(c[2]), "+f"(c[3])
                 : "r"(a[0]), "r"(a[1]), "r"(a[2]), "r"(a[3]), "r"(b0), "r"(b1));
}
__device__ __forceinline__ void cp_async16(uint32_t dst, const void* src) {
    asm volatile("cp.async.ca.shared.global [%0], [%1], 16;"
                 :: "r"(dst), "l"(src) : "memory");
}

// ---- Prep kernel: rn-split E table into bf16 hi/lo (rows 0..255) ----
// 128 blocks x 256 threads, one float4 each: 32768 quads = 256*512 floats.
__global__ __launch_bounds__(256)
void esplit_kernel(const float* __restrict__ et) {
    const int i = blockIdx.x * 256 + threadIdx.x;    // quad index
    const float4 v = *(const float4*)&et[(size_t)i * 4];
    const float hx = __bfloat162float(__float2bfloat16_rn(v.x));
    const float hy = __bfloat162float(__float2bfloat16_rn(v.y));
    const float hz = __bfloat162float(__float2bfloat16_rn(v.z));
    const float hw = __bfloat162float(__float2bfloat16_rn(v.w));
    *(uint2*)&g_ehi[(size_t)i * 4] = make_uint2(pack2(hx, hy), pack2(hz, hw));
    *(uint2*)&g_elo[(size_t)i * 4] =
        make_uint2(pack2(v.x - hx, v.y - hy), pack2(v.z - hz, v.w - hw));
}

// ---- Main fused kernel: HMMA core, 512 threads, 2 blocks/SM ----
// Grid = (16 qtiles, 16 b*h) = 256 blocks.
// Phase 1: Pu[32,256] = Qhi·Ehi^T + Qhi·Elo^T + Qlo·Ehi^T  (split-bf16, fp32 acc)
// Phase 2: out[b,h,q0+qi,k] = Pu[qi][ mx + x[b,k] - x[b,q0+qi] ]
__global__ __launch_bounds__(NT)
void relpos_hmma_kernel(const float* __restrict__ qin,
                        const int*   __restrict__ xw,
                        const int*   __restrict__ mxp,
                        float*       __restrict__ out)
{
    extern __shared__ char tiles[];
    __shared__ int sX[Ss];
    __shared__ int sIs64;

    const uint32_t tb = smem_u32(tiles);
    const int tid  = threadIdx.x;
    const int lane = tid & 31;
    const int w    = tid >> 5;            // 0..15
    const int q0   = blockIdx.x * QT;
    const int h    = blockIdx.y & 7;
    const int b    = blockIdx.y >> 3;

    if (tid == 0) sIs64 = 1;

    // ---- E tiles: pure cp.async of pre-split bf16 (2 tables x 256 rows x 8 chunks) ----
    #pragma unroll
    for (int i = tid; i < 2 * NRU * 8; i += NT) {    // 8 iters/thread
        const int tbl = i >> 11;                     // 0 = hi, 1 = lo
        const int r   = (i >> 3) & 255;
        const int c   = i & 7;                       // 16B chunk within row
        const __nv_bfloat16* src = (tbl ? g_elo : g_ehi) + r * Ee + h * Dd + c * 8;
        cp_async16(tb + (tbl ? OFF_ELO : OFF_EHI) + r * ROWB + c * 16, src);
    }
    asm volatile("cp.async.commit_group;" ::: "memory");

    // ---- Load + split Q (32 x 64): exactly 512 quads, inline rn split ----
    {
        const int qi = tid >> 4, c4 = (tid & 15) * 4;
        const float4 v = *(const float4*)&qin[(((size_t)b * Ss + q0 + qi) * Hh + h) * Dd + c4];
        const float hx = __bfloat162float(__float2bfloat16_rn(v.x));
        const float hy = __bfloat162float(__float2bfloat16_rn(v.y));
        const float hz = __bfloat162float(__float2bfloat16_rn(v.z));
        const float hw = __bfloat162float(__float2bfloat16_rn(v.w));
        const int off = qi * ROWB + c4 * 2;
        *(uint2*)(tiles + OFF_QHI + off) = make_uint2(pack2(hx, hy), pack2(hz, hw));
        *(uint2*)(tiles + OFF_QLO + off) =
            make_uint2(pack2(v.x - hx, v.y - hy), pack2(v.z - hz, v.w - hw));
    }
    // dtype detection: int64 x -> odd 32-bit words of first 2 KB are all zero.
    if (xw[2 * tid + 1] != 0) atomicAnd(&sIs64, 0);
    asm volatile("cp.async.wait_group 0;" ::: "memory");
    __syncthreads();

    // x row, normalized to int32 (sIs64 settled at the barrier above)
    if (sIs64) sX[tid] = xw[2 * (b * Ss + tid)];
    else       sX[tid] = xw[b * Ss + tid];

    // ---- Phase 1: HMMA GEMM. warp w: m-tile mi = w>>3 (16 q), n-block nb = w&7 (32 r) ----
    const int mi = w >> 3;
    const int nb = w & 7;

    float acc[4][4];
    #pragma unroll
    for (int nt = 0; nt < 4; ++nt)
        #pragma unroll
        for (int c = 0; c < 4; ++c) acc[nt][c] = 0.0f;

    const uint32_t aAddrOff = (uint32_t)((mi * 16 + (lane & 15)) * ROWB + (lane >> 4) * 16);
    const uint32_t bAddrOff = (uint32_t)(((((lane >> 3) & 1) * 8 + (lane & 7)) * ROWB)
                                         + (lane >> 4) * 16);

    #pragma unroll
    for (int kc = 0; kc < 4; ++kc) {           // K chunks of 16 (32 B)
        uint32_t ahi[4], alo[4];
        ldsm_x4(ahi, tb + OFF_QHI + aAddrOff + kc * 32);
        ldsm_x4(alo, tb + OFF_QLO + aAddrOff + kc * 32);
        #pragma unroll
        for (int pnt = 0; pnt < 2; ++pnt) {    // pair of n8 tiles per ldsm.x4
            const uint32_t eoff = (uint32_t)((nb * 32 + pnt * 16) * ROWB) + bAddrOff + kc * 32;
            uint32_t bh4[4], bl4[4];
            ldsm_x4(bh4, tb + OFF_EHI + eoff);
            ldsm_x4(bl4, tb + OFF_ELO + eoff);
            mma_bf16_r(acc[2 * pnt],     ahi, bh4[0], bh4[2]);
            mma_bf16_r(acc[2 * pnt],     ahi, bl4[0], bl4[2]);
            mma_bf16_r(acc[2 * pnt],     alo, bh4[0], bh4[2]);
            mma_bf16_r(acc[2 * pnt + 1], ahi, bh4[1], bh4[3]);
            mma_bf16_r(acc[2 * pnt + 1], ahi, bl4[1], bl4[3]);
            mma_bf16_r(acc[2 * pnt + 1], alo, bh4[1], bh4[3]);
        }
    }
    __syncthreads();   // all warps done reading tiles before sPu overlay

    // ---- Stage Pu into smem (overlaying tiles) ----
    float* sPu = (float*)tiles;
    {
        const int row  = mi * 16 + (lane >> 2);
        const int colb = nb * 32 + 2 * (lane & 3);
        #pragma unroll
        for (int nt = 0; nt < 4; ++nt) {
            const int col = colb + nt * 8;
            *(float2*)&sPu[row * PUP + col]       = make_float2(acc[nt][0], acc[nt][1]);
            *(float2*)&sPu[(row + 8) * PUP + col] = make_float2(acc[nt][2], acc[nt][3]);
        }
    }
    __syncthreads();

    // ---- Phase 2: scatter epilogue. Thread t: q row = t>>4, k quads kc2 + 16*it ----
    const int mx  = mxp ? mxp[0] : 128;        // LE low word valid for int32/int64
    const int qi  = tid >> 4;                  // 0..31
    const int kc2 = tid & 15;
    const int off = mx - sX[q0 + qi];
    const float* p = &sPu[qi * PUP];
    float* orow = out + (((size_t)(b * Hh + h) * Ss + q0 + qi)) * Ss;

    #pragma unroll
    for (int it = 0; it < 8; ++it) {
        const int k0 = (kc2 + 16 * it) * 4;
        float4 v;
        v.x = p[off + sX[k0]];
        v.y = p[off + sX[k0 + 1]];
        v.z = p[off + sX[k0 + 2]];
        v.w = p[off + sX[k0 + 3]];
        *(float4*)&orow[k0] = v;               // coalesced STG.128
    }
}

extern "C" void kernel_launch(void* const* d_in, const int* in_sizes, int n_in,
                              void* d_out, int out_size) {
    const float* q   = (const float*)d_in[0];
    const float* et  = (const float*)d_in[1];
    const int*   xw  = (const int*)d_in[2];
    const int*   mxp = (n_in > 3) ? (const int*)d_in[3] : nullptr;
    float*       out = (float*)d_out;
    (void)in_sizes; (void)out_size;

    esplit_kernel<<<128, 256>>>(et);

    cudaFuncSetAttribute(relpos_hmma_kernel,
                         cudaFuncAttributeMaxDynamicSharedMemorySize, DYN_BYTES);

    dim3 grid(Ss / QT, Hh * Bb);              // 16 x 16 = 256 blocks, 2 per SM
    relpos_hmma_kernel<<<grid, NT, DYN_BYTES>>>(q, xw, mxp, out);
}

// round 16
// speedup vs baseline: 1.1805x; 1.1805x over previous
#include <cuda_runtime.h>
#include <cuda_bf16.h>
#include <cstdint>
#include <cstddef>

// Problem constants
#define Bb 2
#define Ss 512
#define Hh 8
#define Dd 64
#define Ee 512
#define QT 64            // q rows per block
#define NRU 256          // relative index r
#define ROWB 144         // bf16 tile row stride in BYTES (16B rotation -> ldmatrix conflict-free)
#define PUP 258          // sPu pitch (even -> float2-aligned staging)
#define NT 1024          // threads per block

// Dynamic smem offsets (bytes)
#define OFF_QHI 0
#define OFF_QLO (QT * ROWB)                   //  9216
#define OFF_EHI (2 * QT * ROWB)               // 18432
#define OFF_ELO (2 * QT * ROWB + NRU * ROWB)  // 55296
#define DYN_BYTES (2 * QT * ROWB + 2 * NRU * ROWB)  // 92160; sPu (64*258*4=66048) overlays

__device__ __forceinline__ uint32_t smem_u32(const void* p) {
    uint32_t a;
    asm("{ .reg .u64 t; cvta.to.shared.u64 t, %1; cvt.u32.u64 %0, t; }" : "=r"(a) : "l"(p));
    return a;
}
__device__ __forceinline__ uint32_t pack2(float a, float b) {
    __nv_bfloat162 t = __floats2bfloat162_rn(a, b);   // .x = a (low half)
    return *reinterpret_cast<uint32_t*>(&t);
}
__device__ __forceinline__ void ldsm_x4(uint32_t (&r)[4], uint32_t addr) {
    asm volatile("ldmatrix.sync.aligned.m8n8.x4.shared.b16 {%0,%1,%2,%3}, [%4];"
                 : "=r"(r[0]), "=r"(r[1]), "=r"(r[2]), "=r"(r[3]) : "r"(addr));
}
__device__ __forceinline__ void ldsm_x2(uint32_t (&r)[2], uint32_t addr) {
    asm volatile("ldmatrix.sync.aligned.m8n8.x2.shared.b16 {%0,%1}, [%2];"
                 : "=r"(r[0]), "=r"(r[1]) : "r"(addr));
}
__device__ __forceinline__ void mma_bf16(float (&c)[4], const uint32_t (&a)[4],
                                         const uint32_t (&b)[2]) {
    asm volatile("mma.sync.aligned.m16n8k16.row.col.f32.bf16.bf16.f32 "
                 "{%0,%1,%2,%3}, {%4,%5,%6,%7}, {%8,%9}, {%0,%1,%2,%3};"
                 : "+f"(c[0]), "+f"(c[1]), "+f"(c[2]), "+f"(c[3])
                 : "r"(a[0]), "r"(a[1]), "r"(a[2]), "r"(a[3]), "r"(b[0]), "r"(b[1]));
}

// ---- Fused kernel, HMMA core, 1024 threads (32 warps) ----
// Grid = (8 qtiles, 16 b*h) = 128 blocks (one wave).
// Phase 1: Pu[64,256] = Qhi·Ehi^T + Qhi·Elo^T + Qlo·Ehi^T  (split-bf16, fp32 acc)
// Phase 2: out[b,h,q0+qi,k] = Pu[qi][ mx + x[b,k] - x[b,q0+qi] ]
//          (each thread owns 2 q-rows sharing the same k indices)
__global__ __launch_bounds__(NT)
void relpos_hmma_kernel(const float* __restrict__ qin,
                        const float* __restrict__ et,
                        const int*   __restrict__ xw,
                        const int*   __restrict__ mxp,
                        float*       __restrict__ out)
{
    extern __shared__ char tiles[];
    __shared__ int sX[Ss];     // holds mx + x[b,k]
    __shared__ int sIs64;

    const uint32_t tb = smem_u32(tiles);
    const int tid  = threadIdx.x;
    const int lane = tid & 31;
    const int w    = tid >> 5;            // 0..31
    const int q0   = blockIdx.x * QT;
    const int h    = blockIdx.y & 7;
    const int b    = blockIdx.y >> 3;
    const int mx   = mxp ? mxp[0] : 128;  // LE low word valid for int32/int64

    if (tid == 0) sIs64 = 1;

    // ---- Load + split E (256 x 64) ----
    #pragma unroll
    for (int i = tid; i < NRU * (Dd / 4); i += NT) {
        const int r = i >> 4, c4 = (i & 15) * 4;
        const float4 v = *(const float4*)&et[r * Ee + h * Dd + c4];
        const float hx = __bfloat162float(__float2bfloat16_rn(v.x));
        const float hy = __bfloat162float(__float2bfloat16_rn(v.y));
        const float hz = __bfloat162float(__float2bfloat16_rn(v.z));
        const float hw = __bfloat162float(__float2bfloat16_rn(v.w));
        const int off = r * ROWB + c4 * 2;
        *(uint2*)(tiles + OFF_EHI + off) = make_uint2(pack2(hx, hy), pack2(hz, hw));
        *(uint2*)(tiles + OFF_ELO + off) =
            make_uint2(pack2(v.x - hx, v.y - hy), pack2(v.z - hz, v.w - hw));
    }
    // ---- Load + split Q (64 x 64): exactly 1024 quads ----
    {
        const int qi = tid >> 4, c4 = (tid & 15) * 4;
        const float4 v = *(const float4*)&qin[(((size_t)b * Ss + q0 + qi) * Hh + h) * Dd + c4];
        const float hx = __bfloat162float(__float2bfloat16_rn(v.x));
        const float hy = __bfloat162float(__float2bfloat16_rn(v.y));
        const float hz = __bfloat162float(__float2bfloat16_rn(v.z));
        const float hw = __bfloat162float(__float2bfloat16_rn(v.w));
        const int off = qi * ROWB + c4 * 2;
        *(uint2*)(tiles + OFF_QHI + off) = make_uint2(pack2(hx, hy), pack2(hz, hw));
        *(uint2*)(tiles + OFF_QLO + off) =
            make_uint2(pack2(v.x - hx, v.y - hy), pack2(v.z - hz, v.w - hw));
    }
    // dtype detection: int64 x -> odd 32-bit words of first 4 KB are all zero.
    if (tid < Ss && xw[2 * tid + 1] != 0) atomicAnd(&sIs64, 0);
    __syncthreads();

    // x row: store mx + x[b,k] (index base pre-added)
    if (tid < Ss) {
        if (sIs64) sX[tid] = mx + xw[2 * (b * Ss + tid)];
        else       sX[tid] = mx + xw[b * Ss + tid];
    }

    // ---- Phase 1: HMMA GEMM. warp w: m-tile mi = w>>3 (16 q), n-block nb = w&7 (32 r) ----
    const int mi = w >> 3;
    const int nb = w & 7;

    float acc[4][4];
    #pragma unroll
    for (int nt = 0; nt < 4; ++nt)
        #pragma unroll
        for (int c = 0; c < 4; ++c) acc[nt][c] = 0.0f;

    const uint32_t aAddrOff = (uint32_t)((mi * 16 + (lane & 15)) * ROWB + (lane >> 4) * 16);
    const uint32_t bRow     = (uint32_t)(lane & 7);
    const uint32_t bColOff  = (uint32_t)(((lane >> 3) & 1) * 16);

    #pragma unroll
    for (int kc = 0; kc < 4; ++kc) {           // K chunks of 16 (32 B)
        uint32_t ahi[4], alo[4];
        ldsm_x4(ahi, tb + OFF_QHI + aAddrOff + kc * 32);
        ldsm_x4(alo, tb + OFF_QLO + aAddrOff + kc * 32);
        #pragma unroll
        for (int nt = 0; nt < 4; ++nt) {
            const uint32_t eoff = (uint32_t)((nb * 32 + nt * 8 + bRow) * ROWB) + bColOff + kc * 32;
            uint32_t bhi[2], blo[2];
            ldsm_x2(bhi, tb + OFF_EHI + eoff);
            ldsm_x2(blo, tb + OFF_ELO + eoff);
            mma_bf16(acc[nt], ahi, bhi);
            mma_bf16(acc[nt], ahi, blo);
            mma_bf16(acc[nt], alo, bhi);
        }
    }
    __syncthreads();   // all warps done reading tiles before sPu overlay

    // ---- Stage Pu into smem (overlaying tiles) ----
    float* sPu = (float*)tiles;
    {
        const int row  = mi * 16 + (lane >> 2);
        const int colb = nb * 32 + 2 * (lane & 3);
        #pragma unroll
        for (int nt = 0; nt < 4; ++nt) {
            const int col = colb + nt * 8;
            *(float2*)&sPu[row * PUP + col]       = make_float2(acc[nt][0], acc[nt][1]);
            *(float2*)&sPu[(row + 8) * PUP + col] = make_float2(acc[nt][2], acc[nt][3]);
        }
    }
    __syncthreads();

    // ---- Phase 2: scatter. Thread t: rows r0 = t>>5 and r0+32; k quads kc + 32*it ----
    const int r0  = tid >> 5;                  // 0..31
    const int kc  = tid & 31;
    const int offA = mx - sX[q0 + r0];         // = -x[q0+r0]
    const int offB = mx - sX[q0 + r0 + 32];
    const float* pA = &sPu[r0 * PUP];
    const float* pB = &sPu[(r0 + 32) * PUP];
    float* orowA = out + (((size_t)(b * Hh + h) * Ss + q0 + r0)) * Ss;
    float* orowB = orowA + (size_t)32 * Ss;

    #pragma unroll
    for (int it = 0; it < 4; ++it) {
        const int k0 = (kc + 32 * it) * 4;
        const int i0 = sX[k0], i1 = sX[k0 + 1], i2 = sX[k0 + 2], i3 = sX[k0 + 3];
        float4 vA, vB;
        vA.x = pA[offA + i0]; vA.y = pA[offA + i1];
        vA.z = pA[offA + i2]; vA.w = pA[offA + i3];
        vB.x = pB[offB + i0]; vB.y = pB[offB + i1];
        vB.z = pB[offB + i2]; vB.w = pB[offB + i3];
        *(float4*)&orowA[k0] = vA;             // coalesced STG.128
        *(float4*)&orowB[k0] = vB;
    }
}

extern "C" void kernel_launch(void* const* d_in, const int* in_sizes, int n_in,
                              void* d_out, int out_size) {
    const float* q   = (const float*)d_in[0];
    const float* et  = (const float*)d_in[1];
    const int*   xw  = (const int*)d_in[2];
    const int*   mxp = (n_in > 3) ? (const int*)d_in[3] : nullptr;
    float*       out = (float*)d_out;
    (void)in_sizes; (void)out_size;

    cudaFuncSetAttribute(relpos_hmma_kernel,
                         cudaFuncAttributeMaxDynamicSharedMemorySize, DYN_BYTES);

    dim3 grid(Ss / QT, Hh * Bb);              // 8 x 16 = 128 blocks (one wave)
    relpos_hmma_kernel<<<grid, NT, DYN_BYTES>>>(q, et, xw, mxp, out);
}